// round 15
// baseline (speedup 1.0000x reference)
#include <cuda_runtime.h>
#include <cuda_bf16.h>
#include <cstdint>

// Problem constants
#define BB 8
#define CHN 512
#define HH 80
#define WW 80
#define HW 6400
#define CR 32

// ---------------- device scratch ----------------
__device__ float g_means[2 * BB * 160 * CHN];   // [z][b][p][c]
__device__ float g_yz[2 * BB * CR * 160];       // [z][b][cr][160]
__device__ float g_s[4 * BB * CHN * 80];        // [a][b][o][80]
__device__ float g_wr[CHN * 1024];              // W fragment-order tf32
__device__ int g_cnt[16];                       // [0..7] mean[b] (tgt 256), [8..15] yz[b] (tgt 40)

// ---------------- helpers ----------------
__device__ __forceinline__ unsigned f2tf32(float x) {
    unsigned u;
    asm("cvt.rna.tf32.f32 %0, %1;" : "=r"(u) : "f"(x));
    return u;
}

__device__ __forceinline__ void mma_tf32(float d[4], const unsigned a0, const unsigned a1,
                                         const unsigned a2, const unsigned a3,
                                         const unsigned b0, const unsigned b1) {
    asm volatile(
        "mma.sync.aligned.m16n8k8.row.col.f32.tf32.tf32.f32 "
        "{%0,%1,%2,%3}, {%4,%5,%6,%7}, {%8,%9}, {%0,%1,%2,%3};\n"
        : "+f"(d[0]), "+f"(d[1]), "+f"(d[2]), "+f"(d[3])
        : "r"(a0), "r"(a1), "r"(a2), "r"(a3), "r"(b0), "r"(b1));
}

#define CP_ASYNC16(dst_u32, src_ptr) \
    asm volatile("cp.async.cg.shared.global [%0], [%1], 16;\n" :: "r"(dst_u32), "l"(src_ptr))
#define CP_COMMIT() asm volatile("cp.async.commit_group;\n" ::)
#define CP_WAITG(n) asm volatile("cp.async.wait_group %0;\n" :: "n"(n))
#define CP_WAIT1()  asm volatile("cp.async.wait_group 1;\n" ::)
#define CP_WAIT0()  asm volatile("cp.async.wait_group 0;\n" ::)

__device__ __forceinline__ void spin_until(const int* cnt, int target) {
    if (threadIdx.x == 0) {
        while (*((volatile int*)cnt) < target) __nanosleep(128);
    }
    __syncthreads();
}
// all threads call: per-thread fence, barrier, t0 atomic
__device__ __forceinline__ void signal(int* cnt) {
    __threadfence();
    __syncthreads();
    if (threadIdx.x == 0) atomicAdd(cnt, 1);
}

// ---------------- kernel W-repack: fragment-order tf32 + counter reset ----------------
__global__ void wrepack_kernel(const float* __restrict__ w) {
    if (blockIdx.x == 0 && threadIdx.x < 16) g_cnt[threadIdx.x] = 0;
    const int blk = blockIdx.x;          // o_blk*32 + kt
    const int o_blk = blk >> 5, kt = blk & 31;
    const int tid = threadIdx.x;
    #pragma unroll
    for (int i = 0; i < 4; ++i) {
        const int gid = tid + i * 256;
        const int lane = gid & 31;
        const int mi = (gid >> 5) & 3;
        const int wm = (gid >> 7) & 1;
        const int kk = (gid >> 8) & 3;
        const int R  = o_blk * 128 + wm * 64 + mi * 16 + (lane >> 2);
        const int Ka = kt * 32 + kk * 8 + (lane & 3);
        uint4 o;
        o.x = f2tf32(w[(size_t)R * 1024 + Ka]);
        o.y = f2tf32(w[(size_t)(R + 8) * 1024 + Ka]);
        o.z = f2tf32(w[(size_t)R * 1024 + Ka + 4]);
        o.w = f2tf32(w[(size_t)(R + 8) * 1024 + Ka + 4]);
        reinterpret_cast<uint4*>(g_wr)[(size_t)blk * 1024 + gid] = o;
    }
}

// ---------------- fused prologue: mean -> yz -> s, single co-resident wave ----------------
#define PRO_SMEM (4 * HW * 4)    // 102400 B -> 2 CTAs/SM

__global__ __launch_bounds__(256, 2)
void pro_kernel(const float* __restrict__ rgb, const float* __restrict__ t,
                const float* __restrict__ w_r1, const float* __restrict__ w_t1,
                const float* __restrict__ bn_g, const float* __restrict__ bn_b,
                const float* __restrict__ bn_m, const float* __restrict__ bn_v,
                const float* __restrict__ w_fh1, const float* __restrict__ w_fw1,
                const float* __restrict__ w_fh2, const float* __restrict__ w_fw2) {
    extern __shared__ float sm[];
    const int tid = threadIdx.x;
    const int bid = blockIdx.x;
    const int G   = gridDim.x;

    // ===== phase M: mean units (2048 units of 4 channels) =====
    for (int u = bid; u < 2048; u += G) {
        const int b = u & 7;
        const int rem = u >> 3;           // 0..255
        const int z = rem & 1;
        const int c0 = (rem >> 1) * 4;    // 0..508
        const float* src = (z ? t : rgb) + ((size_t)(b * CHN) + c0) * HW;

        #pragma unroll
        for (int j = 0; j < 4; ++j) {
            const float* sj = src + (size_t)j * HW;
            float* bj = sm + j * HW;
            for (int i = tid; i < HW / 4; i += 256) {
                unsigned d = (unsigned)__cvta_generic_to_shared(bj + i * 4);
                CP_ASYNC16(d, sj + i * 4);
            }
            CP_COMMIT();
        }
        #pragma unroll
        for (int j = 0; j < 4; ++j) {
            switch (j) {
                case 0: CP_WAITG(3); break;
                case 1: CP_WAITG(2); break;
                case 2: CP_WAITG(1); break;
                default: CP_WAITG(0); break;
            }
            __syncthreads();
            const float* cur = sm + j * HW;
            float* dst = g_means + (((size_t)z * BB + b) * 160) * CHN + c0 + j;
            if (tid < 80) {
                float s = 0.f;
                const float4* r4 = reinterpret_cast<const float4*>(cur + tid * 80);
                #pragma unroll
                for (int w = 0; w < 20; ++w) { float4 v = r4[w]; s += v.x + v.y + v.z + v.w; }
                dst[(size_t)tid * CHN] = s * (1.f / 80.f);
            } else if (tid < 160) {
                const int w = tid - 80;
                float s = 0.f;
                #pragma unroll 8
                for (int h = 0; h < 80; ++h) s += cur[h * 80 + w];
                dst[(size_t)tid * CHN] = s * (1.f / 80.f);
            }
        }
        signal(&g_cnt[b]);      // fence(all) + sync + t0 atomic; sync also guards smem reuse
    }

    // ===== phase Y: yz units (320) =====
    {
        float* w_s = sm;               // 256*33
        float* x_s = sm + 256 * 33;    // 8*256
        for (int u = bid; u < 320; u += G) {
            const int b = u & 7;
            const int rem = u >> 3;    // 0..39
            const int z = rem & 1;
            const int p0 = (rem >> 1) * 8;
            spin_until(&g_cnt[b], 256);    // includes syncthreads (guards smem reuse)
            const float* wsrc = z ? w_t1 : w_r1;
            const float* xbase = g_means + (((size_t)z * BB + b) * 160 + p0) * CHN;
            const int cr = tid & 31;
            const int pl = tid >> 5;
            float acc = 0.f;
            for (int half = 0; half < 2; ++half) {
                if (half) __syncthreads();
                const int c0 = half * 256;
                for (int i = tid; i < 32 * 256; i += 256) {
                    const int cc = i & 255, crr = i >> 8;
                    w_s[cc * 33 + crr] = wsrc[crr * CHN + c0 + cc];
                }
                for (int i = tid; i < 8 * 256; i += 256) {
                    const int ppl = i >> 8, cc = i & 255;
                    x_s[ppl * 256 + cc] = xbase[(size_t)ppl * CHN + c0 + cc];
                }
                __syncthreads();
                #pragma unroll 8
                for (int cc = 0; cc < 256; ++cc)
                    acc += w_s[cc * 33 + cr] * x_s[pl * 256 + cc];
            }
            float s = acc;
            if (z == 0) {
                const float sc = bn_g[cr] * rsqrtf(bn_v[cr] + 1e-5f);
                s = s * sc + (bn_b[cr] - bn_m[cr] * sc);
            }
            s = fmaxf(s, 0.f);
            g_yz[(((size_t)z * BB + b) * CR + cr) * 160 + p0 + pl] = s;
            signal(&g_cnt[8 + b]);
        }
    }

    // ===== phase S: gate units (256) =====
    {
        float* ys  = sm;               // 32*80
        float* wch = sm + CR * 80;     // 64*33
        for (int u = bid; u < 256; u += G) {
            const int b = u & 7;
            const int rem = u >> 3;    // 0..31
            const int a = rem & 3;
            const int oc = rem >> 2;   // 0..7
            spin_until(&g_cnt[8 + b], 40);
            const float* wp = (a == 0) ? w_fh1 : (a == 1) ? w_fw1 : (a == 2) ? w_fh2 : w_fw2;
            const int z = a >> 1;
            const int off = (a & 1) * 80;
            for (int i = tid; i < CR * 80; i += 256) {
                const int cr = i / 80, p = i % 80;
                ys[cr * 80 + p] = g_yz[(((size_t)z * BB + b) * CR + cr) * 160 + off + p];
            }
            for (int i = tid; i < 64 * 32; i += 256) {
                const int ol = i >> 5, cr = i & 31;
                wch[ol * 33 + cr] = wp[(oc * 64 + ol) * CR + cr];
            }
            __syncthreads();
            const int ol = tid >> 2;
            const int hg = (tid & 3) * 20;
            float* dst = g_s + (((size_t)a * BB + b) * CHN + oc * 64 + ol) * 80;
            #pragma unroll
            for (int j = 0; j < 20; ++j) {
                const int h = hg + j;
                float s = 0.f;
                #pragma unroll
                for (int cr = 0; cr < CR; ++cr) s += wch[ol * 33 + cr] * ys[cr * 80 + h];
                dst[h] = 1.f / (1.f + __expf(-s));
            }
            __syncthreads();   // guard smem reuse for next unit
        }
    }
}

// ---------------- kernel C: tf32 mma.sync GEMM (R13, unchanged) ----------------
#define BM 128
#define BN 128
#define BK 32
#define A_STAGE_FLOATS 4096
#define XS_STRIDE 136
#define X_STAGE_FLOATS (BK * XS_STRIDE)
#define STAGE_FLOATS (A_STAGE_FLOATS + X_STAGE_FLOATS)  // 8448
#define NSTAGE 3
#define GEMM_SMEM (NSTAGE * STAGE_FLOATS * 4)           // 101376 bytes
#define NKT 32

struct Frag {
    uint4 a[4];
    unsigned b[8][2];
};

__global__ __launch_bounds__(128, 2)
void gemm_kernel(const float* __restrict__ rgb, const float* __restrict__ t,
                 float* __restrict__ out) {
    extern __shared__ float dynsmem[];

    const int b  = blockIdx.z;
    const int o_blk = blockIdx.y;
    const int o0 = o_blk * BM;
    const int p0 = blockIdx.x * BN;
    const int tid  = threadIdx.x;
    const int lane = tid & 31;
    const int warp = tid >> 5;
    const int wm = warp >> 1;
    const int wn = warp & 1;

    const float* rgbB = rgb + (size_t)b * CHN * HW;
    const float* tB   = t   + (size_t)b * CHN * HW;
    const float* wbase = g_wr + (size_t)o_blk * 32 * A_STAGE_FLOATS;

    float acc[4][8][4];
    #pragma unroll
    for (int i = 0; i < 4; ++i)
        #pragma unroll
        for (int j = 0; j < 8; ++j)
            #pragma unroll
            for (int e = 0; e < 4; ++e) acc[i][j][e] = 0.f;

    auto issue = [&](int stage, int kt) {
        const int k0 = kt * BK;
        const float* xb = (k0 < CHN) ? rgbB : tB;
        const int krow = k0 & (CHN - 1);
        float* As = dynsmem + stage * STAGE_FLOATS;
        float* Xs = As + A_STAGE_FLOATS;
        const float* asrc = wbase + (size_t)kt * A_STAGE_FLOATS;
        #pragma unroll
        for (int ps = 0; ps < 8; ++ps) {
            const int off = (tid + ps * 128) * 4;
            unsigned d = (unsigned)__cvta_generic_to_shared(&As[off]);
            CP_ASYNC16(d, asrc + off);
        }
        #pragma unroll
        for (int ps = 0; ps < 8; ++ps) {
            const int row = (tid >> 5) + ps * 4;
            const int cq  = (tid & 31) * 4;
            unsigned d = (unsigned)__cvta_generic_to_shared(&Xs[row * XS_STRIDE + cq]);
            CP_ASYNC16(d, xb + (size_t)(krow + row) * HW + p0 + cq);
        }
    };

    auto load_frag = [&](Frag& f, const float* As, int kk) {
        const uint4* a4 = reinterpret_cast<const uint4*>(As);
        const float* Xs = As + A_STAGE_FLOATS;
        #pragma unroll
        for (int mi = 0; mi < 4; ++mi)
            f.a[mi] = a4[((kk * 2 + wm) * 4 + mi) * 32 + lane];
        const int ka = kk * 8 + (lane & 3);
        const int cb = wn * 64 + (lane >> 2);
        #pragma unroll
        for (int ni = 0; ni < 8; ++ni) {
            const float* bp = &Xs[ka * XS_STRIDE + cb + ni * 8];
            f.b[ni][0] = f2tf32(bp[0]);
            f.b[ni][1] = f2tf32(bp[4 * XS_STRIDE]);
        }
    };

    auto mma_all = [&](const Frag& f) {
        #pragma unroll
        for (int mi = 0; mi < 4; ++mi)
            #pragma unroll
            for (int ni = 0; ni < 8; ++ni)
                mma_tf32(acc[mi][ni], f.a[mi].x, f.a[mi].y, f.a[mi].z, f.a[mi].w,
                         f.b[ni][0], f.b[ni][1]);
    };

    issue(0, 0); CP_COMMIT();
    issue(1, 1); CP_COMMIT();
    CP_WAIT1();
    __syncthreads();

    Frag fr[2];
    load_frag(fr[0], dynsmem, 0);
    int cur = 0;

    for (int kt = 0; kt < NKT; ++kt) {
        if (kt + 2 < NKT) { issue((kt + 2) % NSTAGE, kt + 2); CP_COMMIT(); }

        const float* As = dynsmem + (kt % NSTAGE) * STAGE_FLOATS;

        #pragma unroll
        for (int kk = 0; kk < 3; ++kk) {
            load_frag(fr[cur ^ 1], As, kk + 1);
            mma_all(fr[cur]);
            cur ^= 1;
        }

        if (kt + 2 < NKT)      CP_WAIT1();
        else if (kt + 1 < NKT) CP_WAIT0();
        __syncthreads();

        mma_all(fr[cur]);
        if (kt + 1 < NKT)
            load_frag(fr[cur ^ 1], dynsmem + ((kt + 1) % NSTAGE) * STAGE_FLOATS, 0);
        cur ^= 1;
    }

    // Epilogue: gate and store
    const float* sh1 = g_s + (((size_t)0 * BB + b) * CHN) * 80;
    const float* sw1 = g_s + (((size_t)1 * BB + b) * CHN) * 80;
    const float* sh2 = g_s + (((size_t)2 * BB + b) * CHN) * 80;
    const float* sw2 = g_s + (((size_t)3 * BB + b) * CHN) * 80;
    float* outB = out + (size_t)b * CHN * HW;

    #pragma unroll
    for (int mi = 0; mi < 4; ++mi) {
        const int r = o0 + wm * 64 + mi * 16 + (lane >> 2);
        #pragma unroll
        for (int ni = 0; ni < 8; ++ni) {
            const int pc = p0 + wn * 64 + ni * 8 + 2 * (lane & 3);
            const int h = pc / 80;
            const int w = pc - h * 80;
            #pragma unroll
            for (int half = 0; half < 2; ++half) {
                const int o = r + half * 8;
                const float sh1v = sh1[o * 80 + h];
                const float sh2v = sh2[o * 80 + h];
                const float g0 = sh1v * sw1[o * 80 + w]     + sh2v * sw2[o * 80 + w];
                const float g1 = sh1v * sw1[o * 80 + w + 1] + sh2v * sw2[o * 80 + w + 1];
                float2 v;
                v.x = acc[mi][ni][half * 2 + 0] * g0;
                v.y = acc[mi][ni][half * 2 + 1] * g1;
                *reinterpret_cast<float2*>(outB + (size_t)o * HW + pc) = v;
            }
        }
    }
}

// ---------------- launch ----------------
extern "C" void kernel_launch(void* const* d_in, const int* in_sizes, int n_in,
                              void* d_out, int out_size) {
    const float* rgb    = (const float*)d_in[0];
    const float* t      = (const float*)d_in[1];
    const float* w_fuse = (const float*)d_in[2];
    const float* w_r1   = (const float*)d_in[3];
    const float* w_t1   = (const float*)d_in[4];
    const float* w_fh1  = (const float*)d_in[5];
    const float* w_fw1  = (const float*)d_in[6];
    const float* w_fh2  = (const float*)d_in[7];
    const float* w_fw2  = (const float*)d_in[8];
    const float* bn_g   = (const float*)d_in[9];
    const float* bn_b   = (const float*)d_in[10];
    const float* bn_m   = (const float*)d_in[11];
    const float* bn_v   = (const float*)d_in[12];
    float* out = (float*)d_out;

    int dev = 0, nsm = 148;
    cudaGetDevice(&dev);
    cudaDeviceGetAttribute(&nsm, cudaDevAttrMultiProcessorCount, dev);

    cudaFuncSetAttribute(gemm_kernel, cudaFuncAttributeMaxDynamicSharedMemorySize, GEMM_SMEM);
    cudaFuncSetAttribute(pro_kernel, cudaFuncAttributeMaxDynamicSharedMemorySize, PRO_SMEM);

    wrepack_kernel<<<128, 256>>>(w_fuse);
    pro_kernel<<<2 * nsm, 256, PRO_SMEM>>>(rgb, t, w_r1, w_t1, bn_g, bn_b, bn_m, bn_v,
                                           w_fh1, w_fw1, w_fh2, w_fw2);
    gemm_kernel<<<dim3(HW / BN, CHN / BM, BB), 128, GEMM_SMEM>>>(rgb, t, out);
}

// round 16
// speedup vs baseline: 1.0482x; 1.0482x over previous
#include <cuda_runtime.h>
#include <cuda_bf16.h>
#include <cstdint>

// Problem constants
#define BB 8
#define CHN 512
#define HH 80
#define WW 80
#define HW 6400
#define CR 32

// ---------------- device scratch ----------------
__device__ float g_means[2 * BB * 160 * CHN];   // [z][b][p][c]
__device__ float g_yz[2 * BB * CR * 160];       // [z][b][cr][160]
__device__ float g_s[4 * BB * CHN * 80];        // [a][b][o][80]
__device__ float g_wr[CHN * 1024];              // W fragment-order tf32

// ---------------- helpers ----------------
__device__ __forceinline__ unsigned f2tf32(float x) {
    unsigned u;
    asm("cvt.rna.tf32.f32 %0, %1;" : "=r"(u) : "f"(x));
    return u;
}

__device__ __forceinline__ void mma_tf32(float d[4], const unsigned a0, const unsigned a1,
                                         const unsigned a2, const unsigned a3,
                                         const unsigned b0, const unsigned b1) {
    asm volatile(
        "mma.sync.aligned.m16n8k8.row.col.f32.tf32.tf32.f32 "
        "{%0,%1,%2,%3}, {%4,%5,%6,%7}, {%8,%9}, {%0,%1,%2,%3};\n"
        : "+f"(d[0]), "+f"(d[1]), "+f"(d[2]), "+f"(d[3])
        : "r"(a0), "r"(a1), "r"(a2), "r"(a3), "r"(b0), "r"(b1));
}

#define CP_ASYNC16(dst_u32, src_ptr) \
    asm volatile("cp.async.cg.shared.global [%0], [%1], 16;\n" :: "r"(dst_u32), "l"(src_ptr))
#define CP_COMMIT() asm volatile("cp.async.commit_group;\n" ::)
#define CP_WAIT1()  asm volatile("cp.async.wait_group 1;\n" ::)
#define CP_WAIT0()  asm volatile("cp.async.wait_group 0;\n" ::)

// ---------------- kernel A: means (register-direct) + wrepack (extra x-blocks) ----------------
// grid (CHN + 8, BB, 2), 256 threads.
//  x < 512 : mean of channel x for (b, z). One warp = 10 rows, lanes 0-19 load float4.
//  x >= 512: wrepack unit idx = (x-512)*16 + b*2 + z  (0..127)
__global__ __launch_bounds__(256)
void mean_kernel(const float* __restrict__ rgb, const float* __restrict__ t,
                 const float* __restrict__ w_fuse) {
    const int b = blockIdx.y;
    const int z = blockIdx.z;
    const int tid = threadIdx.x;

    if (blockIdx.x >= CHN) {
        // ---- wrepack unit ----
        const int blk = (blockIdx.x - CHN) * 16 + b * 2 + z;   // 0..127 = o_blk*32 + kt
        const int o_blk = blk >> 5, kt = blk & 31;
        #pragma unroll
        for (int i = 0; i < 4; ++i) {
            const int gid = tid + i * 256;
            const int lane = gid & 31;
            const int mi = (gid >> 5) & 3;
            const int wm = (gid >> 7) & 1;
            const int kk = (gid >> 8) & 3;
            const int R  = o_blk * 128 + wm * 64 + mi * 16 + (lane >> 2);
            const int Ka = kt * 32 + kk * 8 + (lane & 3);
            uint4 o;
            o.x = f2tf32(w_fuse[(size_t)R * 1024 + Ka]);
            o.y = f2tf32(w_fuse[(size_t)(R + 8) * 1024 + Ka]);
            o.z = f2tf32(w_fuse[(size_t)R * 1024 + Ka + 4]);
            o.w = f2tf32(w_fuse[(size_t)(R + 8) * 1024 + Ka + 4]);
            reinterpret_cast<uint4*>(g_wr)[(size_t)blk * 1024 + gid] = o;
        }
        return;
    }

    // ---- mean of one channel ----
    const int c = blockIdx.x;
    const float* src = (z ? t : rgb) + ((size_t)(b * CHN) + c) * HW;
    const int warp = tid >> 5;
    const int lane = tid & 31;

    __shared__ __align__(16) float sm_w[8][80];
    __shared__ float sm_h[80];

    const int row0 = warp * 10;
    float4 v[10];
    if (lane < 20) {
        #pragma unroll
        for (int r = 0; r < 10; ++r)
            v[r] = reinterpret_cast<const float4*>(src + (size_t)(row0 + r) * 80)[lane];
    } else {
        #pragma unroll
        for (int r = 0; r < 10; ++r) v[r] = make_float4(0.f, 0.f, 0.f, 0.f);
    }

    float wp0 = 0.f, wp1 = 0.f, wp2 = 0.f, wp3 = 0.f;
    #pragma unroll
    for (int r = 0; r < 10; ++r) {
        float hp = (v[r].x + v[r].y) + (v[r].z + v[r].w);
        #pragma unroll
        for (int off = 16; off; off >>= 1)
            hp += __shfl_down_sync(0xFFFFFFFFu, hp, off);
        if (lane == 0) sm_h[row0 + r] = hp;
        wp0 += v[r].x; wp1 += v[r].y; wp2 += v[r].z; wp3 += v[r].w;
    }
    if (lane < 20) {
        float4 wv = make_float4(wp0, wp1, wp2, wp3);
        reinterpret_cast<float4*>(&sm_w[warp][4 * lane])[0] = wv;
    }
    __syncthreads();

    float* dst = g_means + (((size_t)z * BB + b) * 160) * CHN + c;
    if (tid < 80) {
        dst[(size_t)tid * CHN] = sm_h[tid] * (1.f / 80.f);
    } else if (tid < 160) {
        const int wi = tid - 80;
        float s = 0.f;
        #pragma unroll
        for (int w8 = 0; w8 < 8; ++w8) s += sm_w[w8][wi];
        dst[(size_t)tid * CHN] = s * (1.f / 80.f);
    }
}

// ---------------- kernel B1: tiny GEMM + BN/relu ----------------
__global__ void yz_kernel(const float* __restrict__ w_r1, const float* __restrict__ w_t1,
                          const float* __restrict__ bn_g, const float* __restrict__ bn_b,
                          const float* __restrict__ bn_m, const float* __restrict__ bn_v) {
    const int p0 = blockIdx.x * 8;
    const int b  = blockIdx.y;
    const int z  = blockIdx.z;
    const float* wsrc = z ? w_t1 : w_r1;
    const float* xbase = g_means + (((size_t)z * BB + b) * 160 + p0) * CHN;

    __shared__ float w_s[256 * 33];
    __shared__ float x_s[8 * 256];

    const int tid = threadIdx.x;
    const int cr = tid & 31;
    const int pl = tid >> 5;
    float acc = 0.f;

    for (int half = 0; half < 2; ++half) {
        if (half) __syncthreads();
        const int c0 = half * 256;
        for (int j = tid; j < 32 * 256; j += 256) {
            const int cc = j & 255, crr = j >> 8;
            w_s[cc * 33 + crr] = wsrc[crr * CHN + c0 + cc];
        }
        for (int j = tid; j < 8 * 256; j += 256) {
            const int ppl = j >> 8, cc = j & 255;
            x_s[ppl * 256 + cc] = xbase[(size_t)ppl * CHN + c0 + cc];
        }
        __syncthreads();
        #pragma unroll 8
        for (int cc = 0; cc < 256; ++cc)
            acc += w_s[cc * 33 + cr] * x_s[pl * 256 + cc];
    }

    float s = acc;
    if (z == 0) {
        const float sc = bn_g[cr] * rsqrtf(bn_v[cr] + 1e-5f);
        s = s * sc + (bn_b[cr] - bn_m[cr] * sc);
    }
    s = fmaxf(s, 0.f);
    g_yz[(((size_t)z * BB + b) * CR + cr) * 160 + p0 + pl] = s;
}

// ---------------- kernel B2: sigmoid gates (register accumulators, float4 loads/stores) ----------------
__global__ void s_kernel(const float* __restrict__ w_fh1, const float* __restrict__ w_fw1,
                         const float* __restrict__ w_fh2, const float* __restrict__ w_fw2) {
    const int a  = blockIdx.x;
    const int b  = blockIdx.y;
    const int oc = blockIdx.z;
    const float* wp = (a == 0) ? w_fh1 : (a == 1) ? w_fw1 : (a == 2) ? w_fh2 : w_fw2;
    const int z = a >> 1;
    const int off = (a & 1) * 80;

    __shared__ __align__(16) float ys[CR][80];
    __shared__ float wch[64][33];

    const int tid = threadIdx.x;
    for (int i = tid; i < CR * 80; i += 256) {
        const int cr = i / 80, p = i % 80;
        ys[cr][p] = g_yz[(((size_t)z * BB + b) * CR + cr) * 160 + off + p];
    }
    for (int i = tid; i < 64 * 32; i += 256) {
        const int ol = i >> 5, cr = i & 31;
        wch[ol][cr] = wp[(oc * 64 + ol) * CR + cr];
    }
    __syncthreads();

    const int ol = tid >> 2;
    const int hg = (tid & 3) * 20;

    float accum[20];
    #pragma unroll
    for (int j = 0; j < 20; ++j) accum[j] = 0.f;

    #pragma unroll 4
    for (int cr = 0; cr < CR; ++cr) {
        const float wv = wch[ol][cr];
        const float4* yr = reinterpret_cast<const float4*>(&ys[cr][hg]);
        #pragma unroll
        for (int q = 0; q < 5; ++q) {
            float4 v = yr[q];
            accum[q * 4 + 0] += wv * v.x;
            accum[q * 4 + 1] += wv * v.y;
            accum[q * 4 + 2] += wv * v.z;
            accum[q * 4 + 3] += wv * v.w;
        }
    }

    float* dst = g_s + (((size_t)a * BB + b) * CHN + oc * 64 + ol) * 80 + hg;
    #pragma unroll
    for (int q = 0; q < 5; ++q) {
        float4 o;
        o.x = 1.f / (1.f + __expf(-accum[q * 4 + 0]));
        o.y = 1.f / (1.f + __expf(-accum[q * 4 + 1]));
        o.z = 1.f / (1.f + __expf(-accum[q * 4 + 2]));
        o.w = 1.f / (1.f + __expf(-accum[q * 4 + 3]));
        reinterpret_cast<float4*>(dst)[q] = o;
    }
}

// ---------------- kernel C: tf32 mma.sync GEMM (R13, unchanged) ----------------
#define BM 128
#define BN 128
#define BK 32
#define A_STAGE_FLOATS 4096
#define XS_STRIDE 136
#define X_STAGE_FLOATS (BK * XS_STRIDE)
#define STAGE_FLOATS (A_STAGE_FLOATS + X_STAGE_FLOATS)  // 8448
#define NSTAGE 3
#define GEMM_SMEM (NSTAGE * STAGE_FLOATS * 4)           // 101376 bytes
#define NKT 32

struct Frag {
    uint4 a[4];
    unsigned b[8][2];
};

__global__ __launch_bounds__(128, 2)
void gemm_kernel(const float* __restrict__ rgb, const float* __restrict__ t,
                 float* __restrict__ out) {
    extern __shared__ float dynsmem[];

    const int b  = blockIdx.z;
    const int o_blk = blockIdx.y;
    const int o0 = o_blk * BM;
    const int p0 = blockIdx.x * BN;
    const int tid  = threadIdx.x;
    const int lane = tid & 31;
    const int warp = tid >> 5;
    const int wm = warp >> 1;
    const int wn = warp & 1;

    const float* rgbB = rgb + (size_t)b * CHN * HW;
    const float* tB   = t   + (size_t)b * CHN * HW;
    const float* wbase = g_wr + (size_t)o_blk * 32 * A_STAGE_FLOATS;

    float acc[4][8][4];
    #pragma unroll
    for (int i = 0; i < 4; ++i)
        #pragma unroll
        for (int j = 0; j < 8; ++j)
            #pragma unroll
            for (int e = 0; e < 4; ++e) acc[i][j][e] = 0.f;

    auto issue = [&](int stage, int kt) {
        const int k0 = kt * BK;
        const float* xb = (k0 < CHN) ? rgbB : tB;
        const int krow = k0 & (CHN - 1);
        float* As = dynsmem + stage * STAGE_FLOATS;
        float* Xs = As + A_STAGE_FLOATS;
        const float* asrc = wbase + (size_t)kt * A_STAGE_FLOATS;
        #pragma unroll
        for (int ps = 0; ps < 8; ++ps) {
            const int off = (tid + ps * 128) * 4;
            unsigned d = (unsigned)__cvta_generic_to_shared(&As[off]);
            CP_ASYNC16(d, asrc + off);
        }
        #pragma unroll
        for (int ps = 0; ps < 8; ++ps) {
            const int row = (tid >> 5) + ps * 4;
            const int cq  = (tid & 31) * 4;
            unsigned d = (unsigned)__cvta_generic_to_shared(&Xs[row * XS_STRIDE + cq]);
            CP_ASYNC16(d, xb + (size_t)(krow + row) * HW + p0 + cq);
        }
    };

    auto load_frag = [&](Frag& f, const float* As, int kk) {
        const uint4* a4 = reinterpret_cast<const uint4*>(As);
        const float* Xs = As + A_STAGE_FLOATS;
        #pragma unroll
        for (int mi = 0; mi < 4; ++mi)
            f.a[mi] = a4[((kk * 2 + wm) * 4 + mi) * 32 + lane];
        const int ka = kk * 8 + (lane & 3);
        const int cb = wn * 64 + (lane >> 2);
        #pragma unroll
        for (int ni = 0; ni < 8; ++ni) {
            const float* bp = &Xs[ka * XS_STRIDE + cb + ni * 8];
            f.b[ni][0] = f2tf32(bp[0]);
            f.b[ni][1] = f2tf32(bp[4 * XS_STRIDE]);
        }
    };

    auto mma_all = [&](const Frag& f) {
        #pragma unroll
        for (int mi = 0; mi < 4; ++mi)
            #pragma unroll
            for (int ni = 0; ni < 8; ++ni)
                mma_tf32(acc[mi][ni], f.a[mi].x, f.a[mi].y, f.a[mi].z, f.a[mi].w,
                         f.b[ni][0], f.b[ni][1]);
    };

    issue(0, 0); CP_COMMIT();
    issue(1, 1); CP_COMMIT();
    CP_WAIT1();
    __syncthreads();

    Frag fr[2];
    load_frag(fr[0], dynsmem, 0);
    int cur = 0;

    for (int kt = 0; kt < NKT; ++kt) {
        if (kt + 2 < NKT) { issue((kt + 2) % NSTAGE, kt + 2); CP_COMMIT(); }

        const float* As = dynsmem + (kt % NSTAGE) * STAGE_FLOATS;

        #pragma unroll
        for (int kk = 0; kk < 3; ++kk) {
            load_frag(fr[cur ^ 1], As, kk + 1);
            mma_all(fr[cur]);
            cur ^= 1;
        }

        if (kt + 2 < NKT)      CP_WAIT1();
        else if (kt + 1 < NKT) CP_WAIT0();
        __syncthreads();

        mma_all(fr[cur]);
        if (kt + 1 < NKT)
            load_frag(fr[cur ^ 1], dynsmem + ((kt + 1) % NSTAGE) * STAGE_FLOATS, 0);
        cur ^= 1;
    }

    // Epilogue: gate and store
    const float* sh1 = g_s + (((size_t)0 * BB + b) * CHN) * 80;
    const float* sw1 = g_s + (((size_t)1 * BB + b) * CHN) * 80;
    const float* sh2 = g_s + (((size_t)2 * BB + b) * CHN) * 80;
    const float* sw2 = g_s + (((size_t)3 * BB + b) * CHN) * 80;
    float* outB = out + (size_t)b * CHN * HW;

    #pragma unroll
    for (int mi = 0; mi < 4; ++mi) {
        const int r = o0 + wm * 64 + mi * 16 + (lane >> 2);
        #pragma unroll
        for (int ni = 0; ni < 8; ++ni) {
            const int pc = p0 + wn * 64 + ni * 8 + 2 * (lane & 3);
            const int h = pc / 80;
            const int w = pc - h * 80;
            #pragma unroll
            for (int half = 0; half < 2; ++half) {
                const int o = r + half * 8;
                const float sh1v = sh1[o * 80 + h];
                const float sh2v = sh2[o * 80 + h];
                const float g0 = sh1v * sw1[o * 80 + w]     + sh2v * sw2[o * 80 + w];
                const float g1 = sh1v * sw1[o * 80 + w + 1] + sh2v * sw2[o * 80 + w + 1];
                float2 v;
                v.x = acc[mi][ni][half * 2 + 0] * g0;
                v.y = acc[mi][ni][half * 2 + 1] * g1;
                *reinterpret_cast<float2*>(outB + (size_t)o * HW + pc) = v;
            }
        }
    }
}

// ---------------- launch ----------------
extern "C" void kernel_launch(void* const* d_in, const int* in_sizes, int n_in,
                              void* d_out, int out_size) {
    const float* rgb    = (const float*)d_in[0];
    const float* t      = (const float*)d_in[1];
    const float* w_fuse = (const float*)d_in[2];
    const float* w_r1   = (const float*)d_in[3];
    const float* w_t1   = (const float*)d_in[4];
    const float* w_fh1  = (const float*)d_in[5];
    const float* w_fw1  = (const float*)d_in[6];
    const float* w_fh2  = (const float*)d_in[7];
    const float* w_fw2  = (const float*)d_in[8];
    const float* bn_g   = (const float*)d_in[9];
    const float* bn_b   = (const float*)d_in[10];
    const float* bn_m   = (const float*)d_in[11];
    const float* bn_v   = (const float*)d_in[12];
    float* out = (float*)d_out;

    cudaFuncSetAttribute(gemm_kernel, cudaFuncAttributeMaxDynamicSharedMemorySize, GEMM_SMEM);

    mean_kernel<<<dim3(CHN + 8, BB, 2), 256>>>(rgb, t, w_fuse);
    yz_kernel<<<dim3(20, BB, 2), 256>>>(w_r1, w_t1, bn_g, bn_b, bn_m, bn_v);
    s_kernel<<<dim3(4, BB, 8), 256>>>(w_fh1, w_fw1, w_fh2, w_fw2);
    gemm_kernel<<<dim3(HW / BN, CHN / BM, BB), 128, GEMM_SMEM>>>(rgb, t, out);
}

// round 17
// speedup vs baseline: 1.1618x; 1.1084x over previous
#include <cuda_runtime.h>
#include <cuda_bf16.h>
#include <cstdint>

// Problem constants
#define BB 8
#define CHN 512
#define HH 80
#define WW 80
#define HW 6400
#define CR 32

// ---------------- device scratch ----------------
__device__ float g_means[2 * BB * 160 * CHN];   // [z][b][p][c]
__device__ float g_yz[2 * BB * CR * 160];       // [z][b][cr][160]
__device__ float g_s[4 * BB * CHN * 80];        // [a][b][o][80]
__device__ float g_wr[CHN * 1024];              // W fragment-order tf32

// ---------------- helpers ----------------
__device__ __forceinline__ unsigned f2tf32(float x) {
    unsigned u;
    asm("cvt.rna.tf32.f32 %0, %1;" : "=r"(u) : "f"(x));
    return u;
}

__device__ __forceinline__ void mma_tf32(float d[4], const unsigned a0, const unsigned a1,
                                         const unsigned a2, const unsigned a3,
                                         const unsigned b0, const unsigned b1) {
    asm volatile(
        "mma.sync.aligned.m16n8k8.row.col.f32.tf32.tf32.f32 "
        "{%0,%1,%2,%3}, {%4,%5,%6,%7}, {%8,%9}, {%0,%1,%2,%3};\n"
        : "+f"(d[0]), "+f"(d[1]), "+f"(d[2]), "+f"(d[3])
        : "r"(a0), "r"(a1), "r"(a2), "r"(a3), "r"(b0), "r"(b1));
}

#define CP_ASYNC16(dst_u32, src_ptr) \
    asm volatile("cp.async.cg.shared.global [%0], [%1], 16;\n" :: "r"(dst_u32), "l"(src_ptr))
#define CP_COMMIT() asm volatile("cp.async.commit_group;\n" ::)
#define CP_WAIT1()  asm volatile("cp.async.wait_group 1;\n" ::)
#define CP_WAIT0()  asm volatile("cp.async.wait_group 0;\n" ::)

// ---------------- kernel A: means (register-direct) + wrepack (extra x-blocks) ----------------
__global__ __launch_bounds__(256)
void mean_kernel(const float* __restrict__ rgb, const float* __restrict__ t,
                 const float* __restrict__ w_fuse) {
    const int b = blockIdx.y;
    const int z = blockIdx.z;
    const int tid = threadIdx.x;

    if (blockIdx.x >= CHN) {
        // ---- wrepack unit ----
        const int blk = (blockIdx.x - CHN) * 16 + b * 2 + z;   // 0..127 = o_blk*32 + kt
        const int o_blk = blk >> 5, kt = blk & 31;
        #pragma unroll
        for (int i = 0; i < 4; ++i) {
            const int gid = tid + i * 256;
            const int lane = gid & 31;
            const int mi = (gid >> 5) & 3;
            const int wm = (gid >> 7) & 1;
            const int kk = (gid >> 8) & 3;
            const int R  = o_blk * 128 + wm * 64 + mi * 16 + (lane >> 2);
            const int Ka = kt * 32 + kk * 8 + (lane & 3);
            uint4 o;
            o.x = f2tf32(w_fuse[(size_t)R * 1024 + Ka]);
            o.y = f2tf32(w_fuse[(size_t)(R + 8) * 1024 + Ka]);
            o.z = f2tf32(w_fuse[(size_t)R * 1024 + Ka + 4]);
            o.w = f2tf32(w_fuse[(size_t)(R + 8) * 1024 + Ka + 4]);
            reinterpret_cast<uint4*>(g_wr)[(size_t)blk * 1024 + gid] = o;
        }
        return;
    }

    // ---- mean of one channel ----
    const int c = blockIdx.x;
    const float* src = (z ? t : rgb) + ((size_t)(b * CHN) + c) * HW;
    const int warp = tid >> 5;
    const int lane = tid & 31;

    __shared__ __align__(16) float sm_w[8][80];
    __shared__ float sm_h[80];

    const int row0 = warp * 10;
    float4 v[10];
    if (lane < 20) {
        #pragma unroll
        for (int r = 0; r < 10; ++r)
            v[r] = reinterpret_cast<const float4*>(src + (size_t)(row0 + r) * 80)[lane];
    } else {
        #pragma unroll
        for (int r = 0; r < 10; ++r) v[r] = make_float4(0.f, 0.f, 0.f, 0.f);
    }

    float wp0 = 0.f, wp1 = 0.f, wp2 = 0.f, wp3 = 0.f;
    #pragma unroll
    for (int r = 0; r < 10; ++r) {
        float hp = (v[r].x + v[r].y) + (v[r].z + v[r].w);
        #pragma unroll
        for (int off = 16; off; off >>= 1)
            hp += __shfl_down_sync(0xFFFFFFFFu, hp, off);
        if (lane == 0) sm_h[row0 + r] = hp;
        wp0 += v[r].x; wp1 += v[r].y; wp2 += v[r].z; wp3 += v[r].w;
    }
    if (lane < 20) {
        float4 wv = make_float4(wp0, wp1, wp2, wp3);
        reinterpret_cast<float4*>(&sm_w[warp][4 * lane])[0] = wv;
    }
    __syncthreads();

    float* dst = g_means + (((size_t)z * BB + b) * 160) * CHN + c;
    if (tid < 80) {
        dst[(size_t)tid * CHN] = sm_h[tid] * (1.f / 80.f);
    } else if (tid < 160) {
        const int wi = tid - 80;
        float s = 0.f;
        #pragma unroll
        for (int w8 = 0; w8 < 8; ++w8) s += sm_w[w8][wi];
        dst[(size_t)tid * CHN] = s * (1.f / 80.f);
    }
}

// ---------------- kernel B1: tiny GEMM + BN/relu ----------------
__global__ void yz_kernel(const float* __restrict__ w_r1, const float* __restrict__ w_t1,
                          const float* __restrict__ bn_g, const float* __restrict__ bn_b,
                          const float* __restrict__ bn_m, const float* __restrict__ bn_v) {
    const int p0 = blockIdx.x * 8;
    const int b  = blockIdx.y;
    const int z  = blockIdx.z;
    const float* wsrc = z ? w_t1 : w_r1;
    const float* xbase = g_means + (((size_t)z * BB + b) * 160 + p0) * CHN;

    __shared__ float w_s[256 * 33];
    __shared__ float x_s[8 * 256];

    const int tid = threadIdx.x;
    const int cr = tid & 31;
    const int pl = tid >> 5;
    float acc = 0.f;

    for (int half = 0; half < 2; ++half) {
        if (half) __syncthreads();
        const int c0 = half * 256;
        for (int j = tid; j < 32 * 256; j += 256) {
            const int cc = j & 255, crr = j >> 8;
            w_s[cc * 33 + crr] = wsrc[crr * CHN + c0 + cc];
        }
        for (int j = tid; j < 8 * 256; j += 256) {
            const int ppl = j >> 8, cc = j & 255;
            x_s[ppl * 256 + cc] = xbase[(size_t)ppl * CHN + c0 + cc];
        }
        __syncthreads();
        #pragma unroll 8
        for (int cc = 0; cc < 256; ++cc)
            acc += w_s[cc * 33 + cr] * x_s[pl * 256 + cc];
    }

    float s = acc;
    if (z == 0) {
        const float sc = bn_g[cr] * rsqrtf(bn_v[cr] + 1e-5f);
        s = s * sc + (bn_b[cr] - bn_m[cr] * sc);
    }
    s = fmaxf(s, 0.f);
    g_yz[(((size_t)z * BB + b) * CR + cr) * 160 + p0 + pl] = s;
}

// ---------------- kernel B2: sigmoid gates ----------------
__global__ void s_kernel(const float* __restrict__ w_fh1, const float* __restrict__ w_fw1,
                         const float* __restrict__ w_fh2, const float* __restrict__ w_fw2) {
    const int a  = blockIdx.x;
    const int b  = blockIdx.y;
    const int oc = blockIdx.z;
    const float* wp = (a == 0) ? w_fh1 : (a == 1) ? w_fw1 : (a == 2) ? w_fh2 : w_fw2;
    const int z = a >> 1;
    const int off = (a & 1) * 80;

    __shared__ __align__(16) float ys[CR][80];
    __shared__ float wch[64][33];

    const int tid = threadIdx.x;
    for (int i = tid; i < CR * 80; i += 256) {
        const int cr = i / 80, p = i % 80;
        ys[cr][p] = g_yz[(((size_t)z * BB + b) * CR + cr) * 160 + off + p];
    }
    for (int i = tid; i < 64 * 32; i += 256) {
        const int ol = i >> 5, cr = i & 31;
        wch[ol][cr] = wp[(oc * 64 + ol) * CR + cr];
    }
    __syncthreads();

    const int ol = tid >> 2;
    const int hg = (tid & 3) * 20;

    float accum[20];
    #pragma unroll
    for (int j = 0; j < 20; ++j) accum[j] = 0.f;

    #pragma unroll 4
    for (int cr = 0; cr < CR; ++cr) {
        const float wv = wch[ol][cr];
        const float4* yr = reinterpret_cast<const float4*>(&ys[cr][hg]);
        #pragma unroll
        for (int q = 0; q < 5; ++q) {
            float4 v = yr[q];
            accum[q * 4 + 0] += wv * v.x;
            accum[q * 4 + 1] += wv * v.y;
            accum[q * 4 + 2] += wv * v.z;
            accum[q * 4 + 3] += wv * v.w;
        }
    }

    float* dst = g_s + (((size_t)a * BB + b) * CHN + oc * 64 + ol) * 80 + hg;
    #pragma unroll
    for (int q = 0; q < 5; ++q) {
        float4 o;
        o.x = 1.f / (1.f + __expf(-accum[q * 4 + 0]));
        o.y = 1.f / (1.f + __expf(-accum[q * 4 + 1]));
        o.z = 1.f / (1.f + __expf(-accum[q * 4 + 2]));
        o.w = 1.f / (1.f + __expf(-accum[q * 4 + 3]));
        reinterpret_cast<float4*>(dst)[q] = o;
    }
}

// ---------------- kernel C: tf32 mma.sync GEMM (B fed raw fp32, HW truncates) ----------------
#define BM 128
#define BN 128
#define BK 32
#define A_STAGE_FLOATS 4096
#define XS_STRIDE 136
#define X_STAGE_FLOATS (BK * XS_STRIDE)
#define STAGE_FLOATS (A_STAGE_FLOATS + X_STAGE_FLOATS)  // 8448
#define NSTAGE 3
#define GEMM_SMEM (NSTAGE * STAGE_FLOATS * 4)           // 101376 bytes
#define NKT 32

struct Frag {
    uint4 a[4];
    unsigned b[8][2];
};

__global__ __launch_bounds__(128, 2)
void gemm_kernel(const float* __restrict__ rgb, const float* __restrict__ t,
                 float* __restrict__ out) {
    extern __shared__ float dynsmem[];

    const int b  = blockIdx.z;
    const int o_blk = blockIdx.y;
    const int o0 = o_blk * BM;
    const int p0 = blockIdx.x * BN;
    const int tid  = threadIdx.x;
    const int lane = tid & 31;
    const int warp = tid >> 5;
    const int wm = warp >> 1;
    const int wn = warp & 1;

    const float* rgbB = rgb + (size_t)b * CHN * HW;
    const float* tB   = t   + (size_t)b * CHN * HW;
    const float* wbase = g_wr + (size_t)o_blk * 32 * A_STAGE_FLOATS;

    float acc[4][8][4];
    #pragma unroll
    for (int i = 0; i < 4; ++i)
        #pragma unroll
        for (int j = 0; j < 8; ++j)
            #pragma unroll
            for (int e = 0; e < 4; ++e) acc[i][j][e] = 0.f;

    auto issue = [&](int stage, int kt) {
        const int k0 = kt * BK;
        const float* xb = (k0 < CHN) ? rgbB : tB;
        const int krow = k0 & (CHN - 1);
        float* As = dynsmem + stage * STAGE_FLOATS;
        float* Xs = As + A_STAGE_FLOATS;
        const float* asrc = wbase + (size_t)kt * A_STAGE_FLOATS;
        // X first (DRAM latency), then A (L2-resident)
        #pragma unroll
        for (int ps = 0; ps < 8; ++ps) {
            const int row = (tid >> 5) + ps * 4;
            const int cq  = (tid & 31) * 4;
            unsigned d = (unsigned)__cvta_generic_to_shared(&Xs[row * XS_STRIDE + cq]);
            CP_ASYNC16(d, xb + (size_t)(krow + row) * HW + p0 + cq);
        }
        #pragma unroll
        for (int ps = 0; ps < 8; ++ps) {
            const int off = (tid + ps * 128) * 4;
            unsigned d = (unsigned)__cvta_generic_to_shared(&As[off]);
            CP_ASYNC16(d, asrc + off);
        }
    };

    auto load_frag = [&](Frag& f, const float* As, int kk) {
        const uint4* a4 = reinterpret_cast<const uint4*>(As);
        const float* Xs = As + A_STAGE_FLOATS;
        #pragma unroll
        for (int mi = 0; mi < 4; ++mi)
            f.a[mi] = a4[((kk * 2 + wm) * 4 + mi) * 32 + lane];
        const int ka = kk * 8 + (lane & 3);
        const int cb = wn * 64 + (lane >> 2);
        #pragma unroll
        for (int ni = 0; ni < 8; ++ni) {
            const float* bp = &Xs[ka * XS_STRIDE + cb + ni * 8];
            // raw bits; HMMA truncates fp32->tf32 in HW (no cvt on critical path)
            f.b[ni][0] = __float_as_uint(bp[0]);
            f.b[ni][1] = __float_as_uint(bp[4 * XS_STRIDE]);
        }
    };

    auto mma_all = [&](const Frag& f) {
        #pragma unroll
        for (int mi = 0; mi < 4; ++mi)
            #pragma unroll
            for (int ni = 0; ni < 8; ++ni)
                mma_tf32(acc[mi][ni], f.a[mi].x, f.a[mi].y, f.a[mi].z, f.a[mi].w,
                         f.b[ni][0], f.b[ni][1]);
    };

    issue(0, 0); CP_COMMIT();
    issue(1, 1); CP_COMMIT();
    CP_WAIT1();
    __syncthreads();

    Frag fr[2];
    load_frag(fr[0], dynsmem, 0);
    int cur = 0;

    for (int kt = 0; kt < NKT; ++kt) {
        if (kt + 2 < NKT) { issue((kt + 2) % NSTAGE, kt + 2); CP_COMMIT(); }

        const float* As = dynsmem + (kt % NSTAGE) * STAGE_FLOATS;

        #pragma unroll
        for (int kk = 0; kk < 3; ++kk) {
            load_frag(fr[cur ^ 1], As, kk + 1);
            mma_all(fr[cur]);
            cur ^= 1;
        }

        if (kt + 2 < NKT)      CP_WAIT1();
        else if (kt + 1 < NKT) CP_WAIT0();
        __syncthreads();

        mma_all(fr[cur]);
        if (kt + 1 < NKT)
            load_frag(fr[cur ^ 1], dynsmem + ((kt + 1) % NSTAGE) * STAGE_FLOATS, 0);
        cur ^= 1;
    }

    // Epilogue: gate and store
    const float* sh1 = g_s + (((size_t)0 * BB + b) * CHN) * 80;
    const float* sw1 = g_s + (((size_t)1 * BB + b) * CHN) * 80;
    const float* sh2 = g_s + (((size_t)2 * BB + b) * CHN) * 80;
    const float* sw2 = g_s + (((size_t)3 * BB + b) * CHN) * 80;
    float* outB = out + (size_t)b * CHN * HW;

    #pragma unroll
    for (int mi = 0; mi < 4; ++mi) {
        const int r = o0 + wm * 64 + mi * 16 + (lane >> 2);
        #pragma unroll
        for (int ni = 0; ni < 8; ++ni) {
            const int pc = p0 + wn * 64 + ni * 8 + 2 * (lane & 3);
            const int h = pc / 80;
            const int w = pc - h * 80;
            #pragma unroll
            for (int half = 0; half < 2; ++half) {
                const int o = r + half * 8;
                const float sh1v = sh1[o * 80 + h];
                const float sh2v = sh2[o * 80 + h];
                const float g0 = sh1v * sw1[o * 80 + w]     + sh2v * sw2[o * 80 + w];
                const float g1 = sh1v * sw1[o * 80 + w + 1] + sh2v * sw2[o * 80 + w + 1];
                float2 v;
                v.x = acc[mi][ni][half * 2 + 0] * g0;
                v.y = acc[mi][ni][half * 2 + 1] * g1;
                *reinterpret_cast<float2*>(outB + (size_t)o * HW + pc) = v;
            }
        }
    }
}

// ---------------- launch ----------------
extern "C" void kernel_launch(void* const* d_in, const int* in_sizes, int n_in,
                              void* d_out, int out_size) {
    const float* rgb    = (const float*)d_in[0];
    const float* t      = (const float*)d_in[1];
    const float* w_fuse = (const float*)d_in[2];
    const float* w_r1   = (const float*)d_in[3];
    const float* w_t1   = (const float*)d_in[4];
    const float* w_fh1  = (const float*)d_in[5];
    const float* w_fw1  = (const float*)d_in[6];
    const float* w_fh2  = (const float*)d_in[7];
    const float* w_fw2  = (const float*)d_in[8];
    const float* bn_g   = (const float*)d_in[9];
    const float* bn_b   = (const float*)d_in[10];
    const float* bn_m   = (const float*)d_in[11];
    const float* bn_v   = (const float*)d_in[12];
    float* out = (float*)d_out;

    cudaFuncSetAttribute(gemm_kernel, cudaFuncAttributeMaxDynamicSharedMemorySize, GEMM_SMEM);

    mean_kernel<<<dim3(CHN + 8, BB, 2), 256>>>(rgb, t, w_fuse);
    yz_kernel<<<dim3(20, BB, 2), 256>>>(w_r1, w_t1, bn_g, bn_b, bn_m, bn_v);
    s_kernel<<<dim3(4, BB, 8), 256>>>(w_fh1, w_fw1, w_fh2, w_fw2);
    gemm_kernel<<<dim3(HW / BN, CHN / BM, BB), 128, GEMM_SMEM>>>(rgb, t, out);
}